// round 1
// baseline (speedup 1.0000x reference)
#include <cuda_runtime.h>
#include <stdint.h>

#define OUTF 8192
#define INF  8192
#define BATCH 32

// 256MB dense scratch for the materialized weight matrix (row-major [OUTF][INF]).
__device__ float g_W[(size_t)OUTF * (size_t)INF];

// ---------------------------------------------------------------------------
// Kernel 1: zero the dense weight scratch (256MB of float4 stores)
// ---------------------------------------------------------------------------
__global__ void zero_w_kernel() {
    const size_t n4 = ((size_t)OUTF * INF) / 4;
    float4* p = reinterpret_cast<float4*>(g_W);
    const float4 z = make_float4(0.f, 0.f, 0.f, 0.f);
    size_t stride = (size_t)gridDim.x * blockDim.x;
    for (size_t i = (size_t)blockIdx.x * blockDim.x + threadIdx.x; i < n4; i += stride)
        p[i] = z;
}

// ---------------------------------------------------------------------------
// Kernel 2: COO scatter  W[row, col] += val   (atomic: duplicates must sum)
// COO streams are read with __ldcs (evict-first) so they do not evict the
// W working set from L2 — the atomics are the expensive part.
// ---------------------------------------------------------------------------
__global__ void scatter_kernel(const float* __restrict__ vals,
                               const int* __restrict__ rows,
                               const int* __restrict__ cols,
                               int nq /* = NNZ/4 */) {
    int stride = gridDim.x * blockDim.x;
    const int4*   r4 = reinterpret_cast<const int4*>(rows);
    const int4*   c4 = reinterpret_cast<const int4*>(cols);
    const float4* v4 = reinterpret_cast<const float4*>(vals);
    for (int i = blockIdx.x * blockDim.x + threadIdx.x; i < nq; i += stride) {
        int4   r = __ldcs(r4 + i);
        int4   c = __ldcs(c4 + i);
        float4 v = __ldcs(v4 + i);
        atomicAdd(&g_W[(size_t)r.x * INF + c.x], v.x);
        atomicAdd(&g_W[(size_t)r.y * INF + c.y], v.y);
        atomicAdd(&g_W[(size_t)r.z * INF + c.z], v.z);
        atomicAdd(&g_W[(size_t)r.w * INF + c.w], v.w);
    }
}

// ---------------------------------------------------------------------------
// Kernel 3: out[b, o] = bias[o]   (epilogue accumulates on top via atomicAdd)
// ---------------------------------------------------------------------------
__global__ void init_out_kernel(const float* __restrict__ bias,
                                float* __restrict__ out) {
    const int n4 = (BATCH * OUTF) / 4;  // 262144/4
    const float4* b4 = reinterpret_cast<const float4*>(bias);
    float4* o4 = reinterpret_cast<float4*>(out);
    int stride = gridDim.x * blockDim.x;
    for (int i = blockIdx.x * blockDim.x + threadIdx.x; i < n4; i += stride) {
        int o = i & (OUTF / 4 - 1);  // column group within a row
        o4[i] = b4[o];
    }
}

// ---------------------------------------------------------------------------
// Kernel 4: dense GEMM  out[b,o] += sum_k in[b,k] * W[o,k]
// Both operands are k-contiguous row-major -> "NT"-style tiling.
// Block: 256 threads, C-tile 32(b) x 128(o), k-split 2 (grid 64 x 2 = 128
// blocks ~ 1 wave on 148 SMs). Register prefetch double-buffers the smem tile.
// ---------------------------------------------------------------------------
#define OTILE 128
#define KSPLIT 2
#define KC 32

__global__ __launch_bounds__(256, 1)
void gemm_kernel(const float* __restrict__ in, float* __restrict__ out) {
    __shared__ float As[KC][BATCH];   // [k][b]
    __shared__ float Bs[KC][OTILE];   // [k][o]

    const int tid = threadIdx.x;
    const int ob  = blockIdx.x * OTILE;
    const int k0  = blockIdx.y * (INF / KSPLIT);
    const int NT  = (INF / KSPLIT) / KC;  // 128 tiles

    // loader mapping for As (32x32): thread -> (b, 4 consecutive k)
    const int lb = tid >> 3;          // 0..31
    const int lk = (tid & 7) << 2;    // 0,4,...,28
    // loader mapping for Bs (32x128): thread -> (o, 16 consecutive k as 4xfloat4)
    const int wo = tid >> 1;          // 0..127
    const int wk = (tid & 1) << 4;    // 0 or 16
    // compute mapping: thread tile 4(b) x 4(o)
    const int b0 = (tid & 7) << 2;    // 0,4,...,28
    const int o0 = (tid >> 3) << 2;   // 0,4,...,124

    const float* ap = in + (size_t)lb * INF + k0 + lk;
    const float* wp = g_W + (size_t)(ob + wo) * INF + k0 + wk;

    float acc[4][4];
#pragma unroll
    for (int i = 0; i < 4; i++)
#pragma unroll
        for (int j = 0; j < 4; j++) acc[i][j] = 0.f;

    // prefetch tile 0 into registers
    float4 pa = *reinterpret_cast<const float4*>(ap);
    float4 pb[4];
#pragma unroll
    for (int c = 0; c < 4; c++)
        pb[c] = *reinterpret_cast<const float4*>(wp + 4 * c);

    for (int t = 0; t < NT; t++) {
        // commit prefetched tile to smem
        As[lk + 0][lb] = pa.x;
        As[lk + 1][lb] = pa.y;
        As[lk + 2][lb] = pa.z;
        As[lk + 3][lb] = pa.w;
#pragma unroll
        for (int c = 0; c < 4; c++) {
            Bs[wk + 4 * c + 0][wo] = pb[c].x;
            Bs[wk + 4 * c + 1][wo] = pb[c].y;
            Bs[wk + 4 * c + 2][wo] = pb[c].z;
            Bs[wk + 4 * c + 3][wo] = pb[c].w;
        }
        __syncthreads();

        // prefetch next tile while computing on this one
        if (t + 1 < NT) {
            const float* an = ap + (size_t)(t + 1) * KC;
            const float* wn = wp + (size_t)(t + 1) * KC;
            pa = *reinterpret_cast<const float4*>(an);
#pragma unroll
            for (int c = 0; c < 4; c++)
                pb[c] = *reinterpret_cast<const float4*>(wn + 4 * c);
        }

#pragma unroll
        for (int kk = 0; kk < KC; kk++) {
            float4 a = *reinterpret_cast<const float4*>(&As[kk][b0]);
            float4 b = *reinterpret_cast<const float4*>(&Bs[kk][o0]);
            acc[0][0] += a.x * b.x; acc[0][1] += a.x * b.y;
            acc[0][2] += a.x * b.z; acc[0][3] += a.x * b.w;
            acc[1][0] += a.y * b.x; acc[1][1] += a.y * b.y;
            acc[1][2] += a.y * b.z; acc[1][3] += a.y * b.w;
            acc[2][0] += a.z * b.x; acc[2][1] += a.z * b.y;
            acc[2][2] += a.z * b.z; acc[2][3] += a.z * b.w;
            acc[3][0] += a.w * b.x; acc[3][1] += a.w * b.y;
            acc[3][2] += a.w * b.z; acc[3][3] += a.w * b.w;
        }
        __syncthreads();
    }

    // epilogue: accumulate partials on top of bias-initialized out
#pragma unroll
    for (int i = 0; i < 4; i++)
#pragma unroll
        for (int j = 0; j < 4; j++)
            atomicAdd(&out[(size_t)(b0 + i) * OUTF + ob + o0 + j], acc[i][j]);
}

// ---------------------------------------------------------------------------
// launch: zero W -> scatter COO -> init out=bias -> GEMM accumulate
// inputs (metadata order): in_values f32[32*8192], values f32[NNZ],
//                          indices i32[2*NNZ] (rows then cols), bias f32[8192]
// ---------------------------------------------------------------------------
extern "C" void kernel_launch(void* const* d_in, const int* in_sizes, int n_in,
                              void* d_out, int out_size) {
    const float* in_values = (const float*)d_in[0];
    const float* values    = (const float*)d_in[1];
    const int*   indices   = (const int*)d_in[2];
    const float* bias      = (const float*)d_in[3];
    float*       out       = (float*)d_out;

    const int nnz  = in_sizes[1];
    const int* rows = indices;
    const int* cols = indices + nnz;

    zero_w_kernel<<<4736, 256>>>();
    scatter_kernel<<<4736, 256>>>(values, rows, cols, nnz / 4);
    init_out_kernel<<<256, 256>>>(bias, out);
    dim3 ggrid(OUTF / OTILE, KSPLIT);
    gemm_kernel<<<ggrid, 256>>>(in_values, out);
}

// round 2
// speedup vs baseline: 1.6360x; 1.6360x over previous
#include <cuda_runtime.h>
#include <stdint.h>

#define OUTF 8192
#define INF  8192
#define BATCH 32

typedef unsigned long long u64;

// 256MB dense scratch for the materialized weight matrix (row-major [OUTF][INF]).
__device__ float g_W[(size_t)OUTF * (size_t)INF];

// ---------------------------------------------------------------------------
// Slicing: W rows split into 3 slices of <=2731 rows (~87MB each, fits in
// 126MB L2). Zeroing a slice leaves it dirty-resident in L2; the following
// scatter pass then does L2-hit atomics instead of DRAM RMW.
// ---------------------------------------------------------------------------
#define NSLICE 3
#define SLICE_ROWS 2731

__global__ void zero_slice_kernel(int lo, int hi) {
    size_t n4 = (size_t)(hi - lo) * INF / 4;
    float4* p = reinterpret_cast<float4*>(g_W + (size_t)lo * INF);
    const float4 z = make_float4(0.f, 0.f, 0.f, 0.f);
    size_t stride = (size_t)gridDim.x * blockDim.x;
    for (size_t i = (size_t)blockIdx.x * blockDim.x + threadIdx.x; i < n4; i += stride)
        p[i] = z;
}

// COO scatter restricted to rows in [lo, hi). COO streams read evict-first
// (__ldcs) so they do not evict the resident W slice from L2.
__global__ void scatter_slice_kernel(const float* __restrict__ vals,
                                     const int* __restrict__ rows,
                                     const int* __restrict__ cols,
                                     int nq, int lo, int hi) {
    int stride = gridDim.x * blockDim.x;
    const int4*   r4 = reinterpret_cast<const int4*>(rows);
    const int4*   c4 = reinterpret_cast<const int4*>(cols);
    const float4* v4 = reinterpret_cast<const float4*>(vals);
    for (int i = blockIdx.x * blockDim.x + threadIdx.x; i < nq; i += stride) {
        int4   r = __ldcs(r4 + i);
        int4   c = __ldcs(c4 + i);
        float4 v = __ldcs(v4 + i);
        if (r.x >= lo && r.x < hi) atomicAdd(&g_W[(size_t)r.x * INF + c.x], v.x);
        if (r.y >= lo && r.y < hi) atomicAdd(&g_W[(size_t)r.y * INF + c.y], v.y);
        if (r.z >= lo && r.z < hi) atomicAdd(&g_W[(size_t)r.z * INF + c.z], v.z);
        if (r.w >= lo && r.w < hi) atomicAdd(&g_W[(size_t)r.w * INF + c.w], v.w);
    }
}

// scalar tail (nnz % 4), applied once (not per slice): runs BEFORE slicing
// passes would be wrong (slice not zeroed yet) — instead run per-slice too.
__global__ void scatter_tail_kernel(const float* __restrict__ vals,
                                    const int* __restrict__ rows,
                                    const int* __restrict__ cols,
                                    int start, int nnz, int lo, int hi) {
    int i = start + blockIdx.x * blockDim.x + threadIdx.x;
    if (i < nnz) {
        int r = rows[i];
        if (r >= lo && r < hi) atomicAdd(&g_W[(size_t)r * INF + cols[i]], vals[i]);
    }
}

// ---------------------------------------------------------------------------
// out[b, o] = bias[o]   (GEMM epilogue accumulates on top via atomicAdd)
// ---------------------------------------------------------------------------
__global__ void init_out_kernel(const float* __restrict__ bias,
                                float* __restrict__ out) {
    const int n4 = (BATCH * OUTF) / 4;
    const float4* b4 = reinterpret_cast<const float4*>(bias);
    float4* o4 = reinterpret_cast<float4*>(out);
    int stride = gridDim.x * blockDim.x;
    for (int i = blockIdx.x * blockDim.x + threadIdx.x; i < n4; i += stride) {
        int o = i & (OUTF / 4 - 1);
        o4[i] = b4[o];
    }
}

// ---------------------------------------------------------------------------
// Dense GEMM  out[b,o] += sum_k in[b,k] * W[o,k]
// Block: 128 threads, C-tile 32(b) x 256(o), thread-tile 8(b) x 8(o).
// fma.rn.f32x2 packs 2 FMAs/inst (ptxas never emits FFMA2 from C++).
// KSPLIT=8 -> 256 blocks, 2 blocks/SM.
// ---------------------------------------------------------------------------
#define OTILE 256
#define KC 16
#define KSPLIT 8
#define BS_STRIDE 260   // pad: 16B-aligned LDS.128, ~2-way max STS conflicts
#define AS_STRIDE 36

__device__ __forceinline__ u64 pack2(float lo, float hi) {
    u64 r; asm("mov.b64 %0, {%1, %2};" : "=l"(r) : "f"(lo), "f"(hi)); return r;
}
__device__ __forceinline__ void unpack2(u64 v, float& lo, float& hi) {
    asm("mov.b64 {%0, %1}, %2;" : "=f"(lo), "=f"(hi) : "l"(v));
}
__device__ __forceinline__ u64 fma2(u64 a, u64 b, u64 c) {
    u64 d; asm("fma.rn.f32x2 %0, %1, %2, %3;" : "=l"(d) : "l"(a), "l"(b), "l"(c));
    return d;
}

__global__ __launch_bounds__(128, 2)
void gemm_kernel(const float* __restrict__ in, float* __restrict__ out) {
    __shared__ float As[KC][AS_STRIDE];
    __shared__ float Bs[KC][BS_STRIDE];

    const int tid = threadIdx.x;
    const int ob  = blockIdx.x * OTILE;
    const int k0  = blockIdx.y * (INF / KSPLIT);
    const int NT  = (INF / KSPLIT) / KC;   // 64 tiles

    // As loader: 32b x 4 k-quads, one float4 per thread
    const int lb = tid >> 2;
    const int lk = (tid & 3) << 2;
    // compute mapping: o-quads o0 and o0+128; b run of 8
    const int oq = tid & 31;
    const int bq = tid >> 5;           // == warp id -> As reads broadcast
    const int o0 = oq * 4;
    const int b0 = bq * 8;

    u64 acc[8][4];
#pragma unroll
    for (int i = 0; i < 8; i++)
#pragma unroll
        for (int p = 0; p < 4; p++) acc[i][p] = 0ull;

    const float* aP = in + (size_t)lb * INF + k0 + lk;

    float4 pa, pb[8];
    // prefetch tile 0
    pa = *reinterpret_cast<const float4*>(aP);
#pragma unroll
    for (int j = 0; j < 8; j++) {
        int r = j * 128 + tid;
        int o = r >> 2, k4 = (r & 3) << 2;
        pb[j] = *reinterpret_cast<const float4*>(g_W + (size_t)(ob + o) * INF + k0 + k4);
    }

    for (int t = 0; t < NT; t++) {
        // commit prefetched tile to smem (transposed to [k][b]/[k][o])
        As[lk + 0][lb] = pa.x;
        As[lk + 1][lb] = pa.y;
        As[lk + 2][lb] = pa.z;
        As[lk + 3][lb] = pa.w;
#pragma unroll
        for (int j = 0; j < 8; j++) {
            int r = j * 128 + tid;
            int o = r >> 2, k4 = (r & 3) << 2;
            Bs[k4 + 0][o] = pb[j].x;
            Bs[k4 + 1][o] = pb[j].y;
            Bs[k4 + 2][o] = pb[j].z;
            Bs[k4 + 3][o] = pb[j].w;
        }
        __syncthreads();

        if (t + 1 < NT) {
            const int kt = k0 + (t + 1) * KC;
            pa = *reinterpret_cast<const float4*>(aP + (size_t)(t + 1) * KC);
#pragma unroll
            for (int j = 0; j < 8; j++) {
                int r = j * 128 + tid;
                int o = r >> 2, k4 = (r & 3) << 2;
                pb[j] = *reinterpret_cast<const float4*>(g_W + (size_t)(ob + o) * INF + kt + k4);
            }
        }

#pragma unroll
        for (int kk = 0; kk < KC; kk++) {
            float4 a0 = *reinterpret_cast<const float4*>(&As[kk][b0]);
            float4 a1 = *reinterpret_cast<const float4*>(&As[kk][b0 + 4]);
            float4 w0 = *reinterpret_cast<const float4*>(&Bs[kk][o0]);
            float4 w1 = *reinterpret_cast<const float4*>(&Bs[kk][o0 + 128]);
            u64 bp[4];
            bp[0] = pack2(w0.x, w0.y);
            bp[1] = pack2(w0.z, w0.w);
            bp[2] = pack2(w1.x, w1.y);
            bp[3] = pack2(w1.z, w1.w);
            float av[8] = {a0.x, a0.y, a0.z, a0.w, a1.x, a1.y, a1.z, a1.w};
#pragma unroll
            for (int i = 0; i < 8; i++) {
                u64 aa = pack2(av[i], av[i]);
#pragma unroll
                for (int p = 0; p < 4; p++)
                    acc[i][p] = fma2(aa, bp[p], acc[i][p]);
            }
        }
        __syncthreads();
    }

    // epilogue: accumulate partials on top of bias-initialized out
    const int ocol[4] = {o0, o0 + 2, o0 + 128, o0 + 130};
#pragma unroll
    for (int i = 0; i < 8; i++) {
        float* orow = out + (size_t)(b0 + i) * OUTF + ob;
#pragma unroll
        for (int p = 0; p < 4; p++) {
            float lo, hi;
            unpack2(acc[i][p], lo, hi);
            atomicAdd(orow + ocol[p] + 0, lo);
            atomicAdd(orow + ocol[p] + 1, hi);
        }
    }
}

// ---------------------------------------------------------------------------
// launch: per slice { zero slice -> scatter pass } -> init out=bias -> GEMM
// ---------------------------------------------------------------------------
extern "C" void kernel_launch(void* const* d_in, const int* in_sizes, int n_in,
                              void* d_out, int out_size) {
    const float* in_values = (const float*)d_in[0];
    const float* values    = (const float*)d_in[1];
    const int*   indices   = (const int*)d_in[2];
    const float* bias      = (const float*)d_in[3];
    float*       out       = (float*)d_out;

    const int nnz  = in_sizes[1];
    const int* rows = indices;
    const int* cols = indices + nnz;
    const int nq   = nnz / 4;
    const int tail = nnz - nq * 4;

    for (int s = 0; s < NSLICE; s++) {
        int lo = s * SLICE_ROWS;
        int hi = lo + SLICE_ROWS;
        if (hi > OUTF) hi = OUTF;
        zero_slice_kernel<<<2048, 256>>>(lo, hi);
        scatter_slice_kernel<<<4736, 256>>>(values, rows, cols, nq, lo, hi);
        if (tail > 0)
            scatter_tail_kernel<<<1, 32>>>(values, rows, cols, nq * 4, nnz, lo, hi);
    }

    init_out_kernel<<<256, 256>>>(bias, out);
    dim3 ggrid(OUTF / OTILE, KSPLIT);
    gemm_kernel<<<ggrid, 128>>>(in_values, out);
}